// round 13
// baseline (speedup 1.0000x reference)
#include <cuda_runtime.h>
#include <cuda_bf16.h>
#include <cstdint>

#define F 128
#define NMAX 65536
#define EMAX 1200000
#define SCAN_TILE 1024
#define MAXBLK (NMAX / SCAN_TILE)   // 64
#define XS2 136                     // bf16 stride; conflict-free A frags

// ---------------- scratch (no allocations allowed) ----------------
// g_hist and g_flag are zero at module load; k_agg re-zeroes them each run.
__device__ float          g_xp[NMAX * F];
__device__ float          g_asrc[NMAX];
__device__ float          g_adst[NMAX];
__device__ int            g_hist[NMAX];
__device__ int            g_rowstart[NMAX + 1];
__device__ int            g_rank[EMAX];
__device__ int            g_bsum[MAXBLK];
__device__ int            g_flag[MAXBLK];
__device__ int            g_srcs[EMAX];
__device__ __nv_bfloat16  g_whi[128 * 128];  // W^T split-hi, [n][k]
__device__ __nv_bfloat16  g_wlo[128 * 128];  // W^T split-lo, [n][k]

__device__ __forceinline__ int edge_at(const void* ei, int idx, int is64) {
    if (is64) return (int)((const long long*)ei)[idx];
    return ((const int*)ei)[idx];
}

// per-block dtype detection: warp 0 samples 32 odd 32-bit words
__device__ __forceinline__ int detect_is64_block(const int* ei32, int E, int* s_is64) {
    if (threadIdx.x < 32) {
        int nz = 0;
        long long step = (E > 32) ? (E / 32) : 1;
        long long w = 1 + 2 * (long long)threadIdx.x * step;
        if (w < 2LL * E && ei32[w] != 0) nz = 1;
        unsigned b = __ballot_sync(0xffffffffu, nz);
        if (threadIdx.x == 0) *s_is64 = (b == 0u) ? 1 : 0;
    }
    __syncthreads();
    return *s_is64;
}

__device__ __forceinline__ void mma_bf16(float* d, const uint32_t* a, const uint32_t* b) {
    asm volatile(
        "mma.sync.aligned.m16n8k16.row.col.f32.bf16.bf16.f32 "
        "{%0,%1,%2,%3}, {%4,%5,%6,%7}, {%8,%9}, {%0,%1,%2,%3};\n"
        : "+f"(d[0]), "+f"(d[1]), "+f"(d[2]), "+f"(d[3])
        : "r"(a[0]), "r"(a[1]), "r"(a[2]), "r"(a[3]), "r"(b[0]), "r"(b[1]));
}

// ---------------- 0b) split + transpose W -> bf16 hi/lo [n][k] ----------------
__global__ void k_wsplit(const float* __restrict__ W) {
    int idx = blockIdx.x * blockDim.x + threadIdx.x;   // 16384
    int k = idx >> 7, n = idx & 127;
    float a = W[idx];
    __nv_bfloat16 hi = __float2bfloat16_rn(a);
    __nv_bfloat16 lo = __float2bfloat16_rn(a - __bfloat162float(hi));
    g_whi[n * 128 + k] = hi;
    g_wlo[n * 128 + k] = lo;
}

// ---------------- 1) BF16 split tensor GEMM xp = x@W (+ fused attention logits) ----------------
__global__ void k_gemm(const float* __restrict__ x,
                       const float* __restrict__ att_src, const float* __restrict__ att_dst,
                       int N) {
    __shared__ __nv_bfloat16 xs_hi[64 * XS2];
    __shared__ __nv_bfloat16 xs_lo[64 * XS2];
    __shared__ float att_sh[256];
    __shared__ float sdot[128];

    const int tid  = threadIdx.x;               // 256
    const int lane = tid & 31;
    const int w    = tid >> 5;
    const int g    = lane >> 2;
    const int t    = lane & 3;
    const int warp_m = (w & 1) * 32;
    const int warp_n = (w >> 1) * 32;
    const int row0 = blockIdx.x * 64;

    if (tid < 128) {
        att_sh[tid]       = att_src[tid];
        att_sh[128 + tid] = att_dst[tid];
        sdot[tid] = 0.f;
    }

    {   // load + split x tile into bf16 hi/lo planes
        const float4* x4 = (const float4*)x;
        #pragma unroll
        for (int q = 0; q < 8; ++q) {
            int fi = q * 256 + tid;
            int r = fi >> 5, c4 = fi & 31;
            int gr = row0 + r;
            float4 v = make_float4(0.f, 0.f, 0.f, 0.f);
            if (gr < N) v = x4[gr * 32 + c4];
            __nv_bfloat16 h0 = __float2bfloat16_rn(v.x);
            __nv_bfloat16 h1 = __float2bfloat16_rn(v.y);
            __nv_bfloat16 h2 = __float2bfloat16_rn(v.z);
            __nv_bfloat16 h3 = __float2bfloat16_rn(v.w);
            __nv_bfloat16 l0 = __float2bfloat16_rn(v.x - __bfloat162float(h0));
            __nv_bfloat16 l1 = __float2bfloat16_rn(v.y - __bfloat162float(h1));
            __nv_bfloat16 l2 = __float2bfloat16_rn(v.z - __bfloat162float(h2));
            __nv_bfloat16 l3 = __float2bfloat16_rn(v.w - __bfloat162float(h3));
            int off = r * XS2 + c4 * 4;
            *(__nv_bfloat162*)&xs_hi[off]     = __nv_bfloat162(h0, h1);
            *(__nv_bfloat162*)&xs_hi[off + 2] = __nv_bfloat162(h2, h3);
            *(__nv_bfloat162*)&xs_lo[off]     = __nv_bfloat162(l0, l1);
            *(__nv_bfloat162*)&xs_lo[off + 2] = __nv_bfloat162(l2, l3);
        }
    }

    float acc[2][4][4];
    #pragma unroll
    for (int mi = 0; mi < 2; ++mi)
        #pragma unroll
        for (int ni = 0; ni < 4; ++ni)
            #pragma unroll
            for (int q = 0; q < 4; ++q) acc[mi][ni][q] = 0.f;

    __syncthreads();

    #pragma unroll
    for (int kt = 0; kt < 8; ++kt) {
        const int k0 = kt * 16 + 2 * t;
        uint32_t aHi[2][4], aLo[2][4];
        #pragma unroll
        for (int mi = 0; mi < 2; ++mi) {
            int r0 = warp_m + mi * 16 + g;
            aHi[mi][0] = *(const uint32_t*)&xs_hi[r0 * XS2 + k0];
            aHi[mi][1] = *(const uint32_t*)&xs_hi[(r0 + 8) * XS2 + k0];
            aHi[mi][2] = *(const uint32_t*)&xs_hi[r0 * XS2 + k0 + 8];
            aHi[mi][3] = *(const uint32_t*)&xs_hi[(r0 + 8) * XS2 + k0 + 8];
            aLo[mi][0] = *(const uint32_t*)&xs_lo[r0 * XS2 + k0];
            aLo[mi][1] = *(const uint32_t*)&xs_lo[(r0 + 8) * XS2 + k0];
            aLo[mi][2] = *(const uint32_t*)&xs_lo[r0 * XS2 + k0 + 8];
            aLo[mi][3] = *(const uint32_t*)&xs_lo[(r0 + 8) * XS2 + k0 + 8];
        }
        uint32_t bHi[4][2], bLo[4][2];
        #pragma unroll
        for (int ni = 0; ni < 4; ++ni) {
            int base = (warp_n + ni * 8 + g) * 128 + k0;
            bHi[ni][0] = *(const uint32_t*)&g_whi[base];
            bHi[ni][1] = *(const uint32_t*)&g_whi[base + 8];
            bLo[ni][0] = *(const uint32_t*)&g_wlo[base];
            bLo[ni][1] = *(const uint32_t*)&g_wlo[base + 8];
        }
        #pragma unroll
        for (int mi = 0; mi < 2; ++mi)
            #pragma unroll
            for (int ni = 0; ni < 4; ++ni) {
                mma_bf16(acc[mi][ni], aHi[mi], bHi[ni]);
                mma_bf16(acc[mi][ni], aLo[mi], bHi[ni]);
                mma_bf16(acc[mi][ni], aHi[mi], bLo[ni]);
            }
    }

    #pragma unroll
    for (int mi = 0; mi < 2; ++mi) {
        int gr = row0 + warp_m + mi * 16 + g;
        #pragma unroll
        for (int ni = 0; ni < 4; ++ni) {
            int col = warp_n + ni * 8 + 2 * t;
            if (gr < N)
                *(float2*)&g_xp[(size_t)gr * 128 + col] =
                    make_float2(acc[mi][ni][0], acc[mi][ni][1]);
            if (gr + 8 < N)
                *(float2*)&g_xp[(size_t)(gr + 8) * 128 + col] =
                    make_float2(acc[mi][ni][2], acc[mi][ni][3]);
        }
    }

    #pragma unroll
    for (int mi = 0; mi < 2; ++mi) {
        #pragma unroll
        for (int h = 0; h < 2; ++h) {
            float ds = 0.f, dd = 0.f;
            #pragma unroll
            for (int ni = 0; ni < 4; ++ni) {
                int col = warp_n + ni * 8 + 2 * t;
                float c0 = acc[mi][ni][h * 2 + 0];
                float c1 = acc[mi][ni][h * 2 + 1];
                ds += c0 * att_sh[col] + c1 * att_sh[col + 1];
                dd += c0 * att_sh[128 + col] + c1 * att_sh[128 + col + 1];
            }
            ds += __shfl_xor_sync(0xffffffffu, ds, 1);
            ds += __shfl_xor_sync(0xffffffffu, ds, 2);
            dd += __shfl_xor_sync(0xffffffffu, dd, 1);
            dd += __shfl_xor_sync(0xffffffffu, dd, 2);
            if (t == 0) {
                int rl = warp_m + mi * 16 + g + h * 8;
                atomicAdd(&sdot[rl], ds);
                atomicAdd(&sdot[64 + rl], dd);
            }
        }
    }
    __syncthreads();
    if (tid < 64) {
        int gr = row0 + tid;
        if (gr < N) {
            g_asrc[gr] = sdot[tid];
            g_adst[gr] = sdot[64 + tid];
        }
    }
}

// ---------------- 2) histogram of dst + per-edge rank (per-block dtype detect) ----------------
__global__ void k_hist(const void* __restrict__ ei, int E) {
    __shared__ int s_is64;
    int is64 = detect_is64_block((const int*)ei, E, &s_is64);
    int base = (blockIdx.x * blockDim.x + threadIdx.x) * 4;
    #pragma unroll
    for (int q = 0; q < 4; ++q) {
        int e = base + q;
        if (e < E) {
            int d = edge_at(ei, E + e, is64);
            g_rank[e] = atomicAdd(&g_hist[d], 1);
        }
    }
}

// ---------------- 3) single-pass scan with decoupled lookback (+ self-loop placement) ----------------
__global__ void k_scanF(int N, int totalEN) {
    __shared__ int wsum[8];
    __shared__ int blktot_sh;
    __shared__ int s_off;
    const int tid = threadIdx.x;
    const int bid = blockIdx.x;
    const int lane = tid & 31, wid = tid >> 5;
    const int i0 = bid * SCAN_TILE + tid * 4;

    int v0 = 0, v1 = 0, v2 = 0, v3 = 0;
    if (i0 + 3 < N) {
        int4 v = *(const int4*)&g_hist[i0];
        v0 = v.x + 1; v1 = v.y + 1; v2 = v.z + 1; v3 = v.w + 1;   // +1 self loop
    } else {
        if (i0 < N)     v0 = g_hist[i0] + 1;
        if (i0 + 1 < N) v1 = g_hist[i0 + 1] + 1;
        if (i0 + 2 < N) v2 = g_hist[i0 + 2] + 1;
        if (i0 + 3 < N) v3 = g_hist[i0 + 3] + 1;
    }
    int s0 = v0, s1 = s0 + v1, s2 = s1 + v2, s3 = s2 + v3;
    int tsum = s3;
    int incl = tsum;
    #pragma unroll
    for (int off = 1; off < 32; off <<= 1) {
        int n = __shfl_up_sync(0xffffffffu, incl, off);
        if (lane >= off) incl += n;
    }
    if (lane == 31) wsum[wid] = incl;
    if (tid == 0) s_off = 0;
    __syncthreads();
    if (wid == 0 && lane < 8) {
        int wv = wsum[lane];
        int wi = wv;
        #pragma unroll
        for (int off = 1; off < 8; off <<= 1) {
            int n = __shfl_up_sync(0xffu, wi, off);
            if (lane >= off) wi += n;
        }
        wsum[lane] = wi - wv;
        if (lane == 7) blktot_sh = wi;
    }
    __syncthreads();

    if (tid == 0) {
        g_bsum[bid] = blktot_sh;
        __threadfence();
        atomicExch(&g_flag[bid], 1);
    }
    if (tid < bid) {   // bid <= 48 < 256
        while (atomicAdd(&g_flag[tid], 0) == 0) { }
        atomicAdd(&s_off, atomicAdd(&g_bsum[tid], 0));
    }
    __syncthreads();
    const int goff = s_off;

    int base = goff + wsum[wid] + (incl - tsum);
    // rowstart + self-loop placement (self loop takes each node's last slot)
    if (i0 < N)     { g_rowstart[i0]     = base;      g_srcs[base + s0 - 1] = i0;     }
    if (i0 + 1 < N) { g_rowstart[i0 + 1] = base + s0; g_srcs[base + s1 - 1] = i0 + 1; }
    if (i0 + 2 < N) { g_rowstart[i0 + 2] = base + s1; g_srcs[base + s2 - 1] = i0 + 2; }
    if (i0 + 3 < N) { g_rowstart[i0 + 3] = base + s2; g_srcs[base + s3 - 1] = i0 + 3; }
    if (bid == 0 && tid == 0) g_rowstart[N] = totalEN;
}

// ---------------- 4) scatter (atomic-free, 4 edges/thread) ----------------
__global__ void k_scatter1(const void* __restrict__ ei, int E) {
    __shared__ int s_is64;
    int is64 = detect_is64_block((const int*)ei, E, &s_is64);
    int base = (blockIdx.x * blockDim.x + threadIdx.x) * 4;

    int d[4], s[4], r[4];
    #pragma unroll
    for (int q = 0; q < 4; ++q) {
        int e = base + q;
        if (e < E) {
            d[q] = edge_at(ei, E + e, is64);
            s[q] = edge_at(ei, e, is64);
            r[q] = g_rank[e];
        }
    }
    int pos[4];
    #pragma unroll
    for (int q = 0; q < 4; ++q) {
        int e = base + q;
        if (e < E) pos[q] = g_rowstart[d[q]] + r[q];
    }
    #pragma unroll
    for (int q = 0; q < 4; ++q) {
        int e = base + q;
        if (e < E) g_srcs[pos[q]] = s[q];
    }
}

// ---------------- 5) online-softmax fused gather: one WARP per dst node ----------------
// epilogue re-zeroes g_hist/g_flag for the next graph replay
__global__ void k_agg(const float* __restrict__ bias, float* __restrict__ out, int N) {
    const int gt = blockIdx.x * blockDim.x + threadIdx.x;
    const int gw = gt >> 5;
    const int lane = threadIdx.x & 31;
    // re-init scratch for next replay (covers all N since grid has N*32 threads)
    if (gt < N) g_hist[gt] = 0;
    if (gt < MAXBLK) g_flag[gt] = 0;
    if (gw >= N) return;

    const int beg = g_rowstart[gw];
    const int end = g_rowstart[gw + 1];
    const float adst = g_adst[gw];

    float m = -3.4e38f;
    float sum = 0.f;
    float4 acc = make_float4(0.f, 0.f, 0.f, 0.f);

    for (int c = beg; c < end; c += 32) {
        int j = c + lane;
        int src = 0;
        float e = -3.4e38f;
        if (j < end) {
            src = g_srcs[j];
            e = g_asrc[src] + adst;
            e = (e >= 0.f) ? e : 0.2f * e;
        }
        float cm = e;
        #pragma unroll
        for (int o = 16; o > 0; o >>= 1) cm = fmaxf(cm, __shfl_xor_sync(0xffffffffu, cm, o));
        float m_new = fmaxf(m, cm);
        float scale = __expf(m - m_new);
        m = m_new;
        sum *= scale;
        acc.x *= scale; acc.y *= scale; acc.z *= scale; acc.w *= scale;

        float w = (j < end) ? __expf(e - m) : 0.f;
        float ws = w;
        #pragma unroll
        for (int o = 16; o > 0; o >>= 1) ws += __shfl_xor_sync(0xffffffffu, ws, o);
        sum += ws;

        int cnt = min(32, end - c);
        if (cnt == 32) {
            #pragma unroll 8
            for (int jj = 0; jj < 32; ++jj) {
                float wj = __shfl_sync(0xffffffffu, w, jj);
                int   sj = __shfl_sync(0xffffffffu, src, jj);
                float4 v = ((const float4*)(g_xp + (size_t)sj * 128))[lane];
                acc.x += wj * v.x; acc.y += wj * v.y;
                acc.z += wj * v.z; acc.w += wj * v.w;
            }
        } else {
            for (int jj = 0; jj < cnt; ++jj) {
                float wj = __shfl_sync(0xffffffffu, w, jj);
                int   sj = __shfl_sync(0xffffffffu, src, jj);
                float4 v = ((const float4*)(g_xp + (size_t)sj * 128))[lane];
                acc.x += wj * v.x; acc.y += wj * v.y;
                acc.z += wj * v.z; acc.w += wj * v.w;
            }
        }
    }

    const float inv = 1.f / sum;
    float4 b4 = ((const float4*)bias)[lane];
    ((float4*)(out + (size_t)gw * 128))[lane] =
        make_float4(acc.x * inv + b4.x, acc.y * inv + b4.y,
                    acc.z * inv + b4.z, acc.w * inv + b4.w);
}

// ---------------- launch (fork-join: edge prep overlaps GEMM) ----------------
extern "C" void kernel_launch(void* const* d_in, const int* in_sizes, int n_in,
                              void* d_out, int out_size) {
    const float* x        = (const float*)d_in[0];
    const float* W        = (const float*)d_in[1];
    const float* att_src  = (const float*)d_in[2];
    const float* att_dst  = (const float*)d_in[3];
    const float* bias     = (const float*)d_in[4];
    const void*  ei       = d_in[5];

    const int N = in_sizes[0] / F;
    const int E = in_sizes[5] / 2;
    const int nblk = (N + SCAN_TILE - 1) / SCAN_TILE;
    float* out = (float*)d_out;

    static cudaStream_t s1 = nullptr;
    static cudaEvent_t e0 = nullptr, e1 = nullptr;
    if (s1 == nullptr) {
        cudaStreamCreateWithFlags(&s1, cudaStreamNonBlocking);
        cudaEventCreateWithFlags(&e0, cudaEventDisableTiming);
        cudaEventCreateWithFlags(&e1, cudaEventDisableTiming);
    }

    // fork: s1 handles the edge-prep chain (independent of GEMM)
    cudaEventRecord(e0, 0);
    cudaStreamWaitEvent(s1, e0, 0);
    k_hist    <<<(E + 1023) / 1024, 256, 0, s1>>>(ei, E);
    k_scanF   <<<nblk, 256, 0, s1>>>(N, E + N);
    k_scatter1<<<(E + 1023) / 1024, 256, 0, s1>>>(ei, E);
    cudaEventRecord(e1, s1);

    // main stream: W split + GEMM in parallel with the prep chain
    k_wsplit <<<64, 256>>>(W);
    k_gemm   <<<(N + 63) / 64, 256>>>(x, att_src, att_dst, N);

    // join, then fused online-softmax aggregation
    cudaStreamWaitEvent(0, e1, 0);
    k_agg    <<<(N + 7) / 8, 256>>>(bias, out, N);
}

// round 14
// speedup vs baseline: 1.0057x; 1.0057x over previous
#include <cuda_runtime.h>
#include <cuda_bf16.h>
#include <cstdint>

#define F 128
#define NMAX 65536
#define EMAX 1200000
#define SCAN_TILE 1024
#define MAXBLK (NMAX / SCAN_TILE)   // 64
#define XS2 136                     // bf16 stride; conflict-free A frags

// ---------------- scratch (no allocations allowed) ----------------
// g_hist and g_flag are zero at module load; k_agg re-zeroes them each run.
__device__ float          g_xp[NMAX * F];
__device__ float          g_asrc[NMAX];
__device__ float          g_adst[NMAX];
__device__ int            g_hist[NMAX];
__device__ int            g_rowstart[NMAX + 1];
__device__ int            g_rank[EMAX];
__device__ int            g_bsum[MAXBLK];
__device__ int            g_flag[MAXBLK];
__device__ int            g_srcs[EMAX];
__device__ __nv_bfloat16  g_whi[128 * 128];  // W^T split-hi, [n][k]
__device__ __nv_bfloat16  g_wlo[128 * 128];  // W^T split-lo, [n][k]

__device__ __forceinline__ int edge_at(const void* ei, int idx, int is64) {
    if (is64) return (int)((const long long*)ei)[idx];
    return ((const int*)ei)[idx];
}

// per-block dtype detection: warp 0 samples 32 odd 32-bit words
__device__ __forceinline__ int detect_is64_block(const int* ei32, int E, int* s_is64) {
    if (threadIdx.x < 32) {
        int nz = 0;
        long long step = (E > 32) ? (E / 32) : 1;
        long long w = 1 + 2 * (long long)threadIdx.x * step;
        if (w < 2LL * E && ei32[w] != 0) nz = 1;
        unsigned b = __ballot_sync(0xffffffffu, nz);
        if (threadIdx.x == 0) *s_is64 = (b == 0u) ? 1 : 0;
    }
    __syncthreads();
    return *s_is64;
}

__device__ __forceinline__ void mma_bf16(float* d, const uint32_t* a, const uint32_t* b) {
    asm volatile(
        "mma.sync.aligned.m16n8k16.row.col.f32.bf16.bf16.f32 "
        "{%0,%1,%2,%3}, {%4,%5,%6,%7}, {%8,%9}, {%0,%1,%2,%3};\n"
        : "+f"(d[0]), "+f"(d[1]), "+f"(d[2]), "+f"(d[3])
        : "r"(a[0]), "r"(a[1]), "r"(a[2]), "r"(a[3]), "r"(b[0]), "r"(b[1]));
}

// ---------------- 0b) split + transpose W -> bf16 hi/lo [n][k] ----------------
__global__ void k_wsplit(const float* __restrict__ W) {
    int idx = blockIdx.x * blockDim.x + threadIdx.x;   // 16384
    int k = idx >> 7, n = idx & 127;
    float a = W[idx];
    __nv_bfloat16 hi = __float2bfloat16_rn(a);
    __nv_bfloat16 lo = __float2bfloat16_rn(a - __bfloat162float(hi));
    g_whi[n * 128 + k] = hi;
    g_wlo[n * 128 + k] = lo;
}

// ---------------- 1) BF16 split tensor GEMM xp = x@W (+ fused attention logits) ----------------
__global__ void k_gemm(const float* __restrict__ x,
                       const float* __restrict__ att_src, const float* __restrict__ att_dst,
                       int N) {
    __shared__ __nv_bfloat16 xs_hi[64 * XS2];
    __shared__ __nv_bfloat16 xs_lo[64 * XS2];
    __shared__ float att_sh[256];
    __shared__ float sdot[128];

    const int tid  = threadIdx.x;               // 256
    const int lane = tid & 31;
    const int w    = tid >> 5;
    const int g    = lane >> 2;
    const int t    = lane & 3;
    const int warp_m = (w & 1) * 32;
    const int warp_n = (w >> 1) * 32;
    const int row0 = blockIdx.x * 64;

    if (tid < 128) {
        att_sh[tid]       = att_src[tid];
        att_sh[128 + tid] = att_dst[tid];
        sdot[tid] = 0.f;
    }

    {   // load + split x tile into bf16 hi/lo planes
        const float4* x4 = (const float4*)x;
        #pragma unroll
        for (int q = 0; q < 8; ++q) {
            int fi = q * 256 + tid;
            int r = fi >> 5, c4 = fi & 31;
            int gr = row0 + r;
            float4 v = make_float4(0.f, 0.f, 0.f, 0.f);
            if (gr < N) v = x4[gr * 32 + c4];
            __nv_bfloat16 h0 = __float2bfloat16_rn(v.x);
            __nv_bfloat16 h1 = __float2bfloat16_rn(v.y);
            __nv_bfloat16 h2 = __float2bfloat16_rn(v.z);
            __nv_bfloat16 h3 = __float2bfloat16_rn(v.w);
            __nv_bfloat16 l0 = __float2bfloat16_rn(v.x - __bfloat162float(h0));
            __nv_bfloat16 l1 = __float2bfloat16_rn(v.y - __bfloat162float(h1));
            __nv_bfloat16 l2 = __float2bfloat16_rn(v.z - __bfloat162float(h2));
            __nv_bfloat16 l3 = __float2bfloat16_rn(v.w - __bfloat162float(h3));
            int off = r * XS2 + c4 * 4;
            *(__nv_bfloat162*)&xs_hi[off]     = __nv_bfloat162(h0, h1);
            *(__nv_bfloat162*)&xs_hi[off + 2] = __nv_bfloat162(h2, h3);
            *(__nv_bfloat162*)&xs_lo[off]     = __nv_bfloat162(l0, l1);
            *(__nv_bfloat162*)&xs_lo[off + 2] = __nv_bfloat162(l2, l3);
        }
    }

    float acc[2][4][4];
    #pragma unroll
    for (int mi = 0; mi < 2; ++mi)
        #pragma unroll
        for (int ni = 0; ni < 4; ++ni)
            #pragma unroll
            for (int q = 0; q < 4; ++q) acc[mi][ni][q] = 0.f;

    __syncthreads();

    #pragma unroll
    for (int kt = 0; kt < 8; ++kt) {
        const int k0 = kt * 16 + 2 * t;
        uint32_t aHi[2][4], aLo[2][4];
        #pragma unroll
        for (int mi = 0; mi < 2; ++mi) {
            int r0 = warp_m + mi * 16 + g;
            aHi[mi][0] = *(const uint32_t*)&xs_hi[r0 * XS2 + k0];
            aHi[mi][1] = *(const uint32_t*)&xs_hi[(r0 + 8) * XS2 + k0];
            aHi[mi][2] = *(const uint32_t*)&xs_hi[r0 * XS2 + k0 + 8];
            aHi[mi][3] = *(const uint32_t*)&xs_hi[(r0 + 8) * XS2 + k0 + 8];
            aLo[mi][0] = *(const uint32_t*)&xs_lo[r0 * XS2 + k0];
            aLo[mi][1] = *(const uint32_t*)&xs_lo[(r0 + 8) * XS2 + k0];
            aLo[mi][2] = *(const uint32_t*)&xs_lo[r0 * XS2 + k0 + 8];
            aLo[mi][3] = *(const uint32_t*)&xs_lo[(r0 + 8) * XS2 + k0 + 8];
        }
        uint32_t bHi[4][2], bLo[4][2];
        #pragma unroll
        for (int ni = 0; ni < 4; ++ni) {
            int base = (warp_n + ni * 8 + g) * 128 + k0;
            bHi[ni][0] = *(const uint32_t*)&g_whi[base];
            bHi[ni][1] = *(const uint32_t*)&g_whi[base + 8];
            bLo[ni][0] = *(const uint32_t*)&g_wlo[base];
            bLo[ni][1] = *(const uint32_t*)&g_wlo[base + 8];
        }
        #pragma unroll
        for (int mi = 0; mi < 2; ++mi)
            #pragma unroll
            for (int ni = 0; ni < 4; ++ni) {
                mma_bf16(acc[mi][ni], aHi[mi], bHi[ni]);
                mma_bf16(acc[mi][ni], aLo[mi], bHi[ni]);
                mma_bf16(acc[mi][ni], aHi[mi], bLo[ni]);
            }
    }

    #pragma unroll
    for (int mi = 0; mi < 2; ++mi) {
        int gr = row0 + warp_m + mi * 16 + g;
        #pragma unroll
        for (int ni = 0; ni < 4; ++ni) {
            int col = warp_n + ni * 8 + 2 * t;
            if (gr < N)
                *(float2*)&g_xp[(size_t)gr * 128 + col] =
                    make_float2(acc[mi][ni][0], acc[mi][ni][1]);
            if (gr + 8 < N)
                *(float2*)&g_xp[(size_t)(gr + 8) * 128 + col] =
                    make_float2(acc[mi][ni][2], acc[mi][ni][3]);
        }
    }

    #pragma unroll
    for (int mi = 0; mi < 2; ++mi) {
        #pragma unroll
        for (int h = 0; h < 2; ++h) {
            float ds = 0.f, dd = 0.f;
            #pragma unroll
            for (int ni = 0; ni < 4; ++ni) {
                int col = warp_n + ni * 8 + 2 * t;
                float c0 = acc[mi][ni][h * 2 + 0];
                float c1 = acc[mi][ni][h * 2 + 1];
                ds += c0 * att_sh[col] + c1 * att_sh[col + 1];
                dd += c0 * att_sh[128 + col] + c1 * att_sh[128 + col + 1];
            }
            ds += __shfl_xor_sync(0xffffffffu, ds, 1);
            ds += __shfl_xor_sync(0xffffffffu, ds, 2);
            dd += __shfl_xor_sync(0xffffffffu, dd, 1);
            dd += __shfl_xor_sync(0xffffffffu, dd, 2);
            if (t == 0) {
                int rl = warp_m + mi * 16 + g + h * 8;
                atomicAdd(&sdot[rl], ds);
                atomicAdd(&sdot[64 + rl], dd);
            }
        }
    }
    __syncthreads();
    if (tid < 64) {
        int gr = row0 + tid;
        if (gr < N) {
            g_asrc[gr] = sdot[tid];
            g_adst[gr] = sdot[64 + tid];
        }
    }
}

// ---------------- 2) histogram of dst + per-edge rank (int4 fast path) ----------------
__global__ void k_hist(const void* __restrict__ ei, int E) {
    __shared__ int s_is64;
    int is64 = detect_is64_block((const int*)ei, E, &s_is64);
    int base = (blockIdx.x * blockDim.x + threadIdx.x) * 4;
    if (!is64 && ((E & 3) == 0) && base + 3 < E) {
        int4 d4 = *(const int4*)((const int*)ei + E + base);
        int r0 = atomicAdd(&g_hist[d4.x], 1);
        int r1 = atomicAdd(&g_hist[d4.y], 1);
        int r2 = atomicAdd(&g_hist[d4.z], 1);
        int r3 = atomicAdd(&g_hist[d4.w], 1);
        *(int4*)&g_rank[base] = make_int4(r0, r1, r2, r3);
    } else {
        #pragma unroll
        for (int q = 0; q < 4; ++q) {
            int e = base + q;
            if (e < E) {
                int d = edge_at(ei, E + e, is64);
                g_rank[e] = atomicAdd(&g_hist[d], 1);
            }
        }
    }
}

// ---------------- 3) single-pass scan with decoupled lookback (+ self-loop placement) ----------------
__global__ void k_scanF(int N, int totalEN) {
    __shared__ int wsum[8];
    __shared__ int blktot_sh;
    __shared__ int s_off;
    const int tid = threadIdx.x;
    const int bid = blockIdx.x;
    const int lane = tid & 31, wid = tid >> 5;
    const int i0 = bid * SCAN_TILE + tid * 4;

    int v0 = 0, v1 = 0, v2 = 0, v3 = 0;
    if (i0 + 3 < N) {
        int4 v = *(const int4*)&g_hist[i0];
        v0 = v.x + 1; v1 = v.y + 1; v2 = v.z + 1; v3 = v.w + 1;   // +1 self loop
    } else {
        if (i0 < N)     v0 = g_hist[i0] + 1;
        if (i0 + 1 < N) v1 = g_hist[i0 + 1] + 1;
        if (i0 + 2 < N) v2 = g_hist[i0 + 2] + 1;
        if (i0 + 3 < N) v3 = g_hist[i0 + 3] + 1;
    }
    int s0 = v0, s1 = s0 + v1, s2 = s1 + v2, s3 = s2 + v3;
    int tsum = s3;
    int incl = tsum;
    #pragma unroll
    for (int off = 1; off < 32; off <<= 1) {
        int n = __shfl_up_sync(0xffffffffu, incl, off);
        if (lane >= off) incl += n;
    }
    if (lane == 31) wsum[wid] = incl;
    if (tid == 0) s_off = 0;
    __syncthreads();
    if (wid == 0 && lane < 8) {
        int wv = wsum[lane];
        int wi = wv;
        #pragma unroll
        for (int off = 1; off < 8; off <<= 1) {
            int n = __shfl_up_sync(0xffu, wi, off);
            if (lane >= off) wi += n;
        }
        wsum[lane] = wi - wv;
        if (lane == 7) blktot_sh = wi;
    }
    __syncthreads();

    if (tid == 0) {
        g_bsum[bid] = blktot_sh;
        __threadfence();
        atomicExch(&g_flag[bid], 1);
    }
    if (tid < bid) {   // bid <= 48 < 256
        while (atomicAdd(&g_flag[tid], 0) == 0) { }
        atomicAdd(&s_off, atomicAdd(&g_bsum[tid], 0));
    }
    __syncthreads();
    const int goff = s_off;

    int base = goff + wsum[wid] + (incl - tsum);
    // rowstart + self-loop placement (self loop takes each node's last slot)
    if (i0 < N)     { g_rowstart[i0]     = base;      g_srcs[base + s0 - 1] = i0;     }
    if (i0 + 1 < N) { g_rowstart[i0 + 1] = base + s0; g_srcs[base + s1 - 1] = i0 + 1; }
    if (i0 + 2 < N) { g_rowstart[i0 + 2] = base + s1; g_srcs[base + s2 - 1] = i0 + 2; }
    if (i0 + 3 < N) { g_rowstart[i0 + 3] = base + s2; g_srcs[base + s3 - 1] = i0 + 3; }
    if (bid == 0 && tid == 0) g_rowstart[N] = totalEN;
}

// ---------------- 4) scatter (atomic-free, int4 fast path) ----------------
__global__ void k_scatter1(const void* __restrict__ ei, int E) {
    __shared__ int s_is64;
    int is64 = detect_is64_block((const int*)ei, E, &s_is64);
    int base = (blockIdx.x * blockDim.x + threadIdx.x) * 4;

    if (!is64 && ((E & 3) == 0) && base + 3 < E) {
        int4 s4 = *(const int4*)((const int*)ei + base);
        int4 d4 = *(const int4*)((const int*)ei + E + base);
        int4 r4 = *(const int4*)&g_rank[base];
        int p0 = g_rowstart[d4.x] + r4.x;
        int p1 = g_rowstart[d4.y] + r4.y;
        int p2 = g_rowstart[d4.z] + r4.z;
        int p3 = g_rowstart[d4.w] + r4.w;
        g_srcs[p0] = s4.x;
        g_srcs[p1] = s4.y;
        g_srcs[p2] = s4.z;
        g_srcs[p3] = s4.w;
    } else {
        int d[4], s[4], r[4];
        #pragma unroll
        for (int q = 0; q < 4; ++q) {
            int e = base + q;
            if (e < E) {
                d[q] = edge_at(ei, E + e, is64);
                s[q] = edge_at(ei, e, is64);
                r[q] = g_rank[e];
            }
        }
        #pragma unroll
        for (int q = 0; q < 4; ++q) {
            int e = base + q;
            if (e < E) g_srcs[g_rowstart[d[q]] + r[q]] = s[q];
        }
    }
}

// ---------------- 5) online-softmax fused gather: one WARP per dst node ----------------
// epilogue re-zeroes g_hist/g_flag for the next graph replay
__global__ void k_agg(const float* __restrict__ bias, float* __restrict__ out, int N) {
    const int gt = blockIdx.x * blockDim.x + threadIdx.x;
    const int gw = gt >> 5;
    const int lane = threadIdx.x & 31;
    // re-init scratch for next replay (covers all N since grid has N*32 threads)
    if (gt < N) g_hist[gt] = 0;
    if (gt < MAXBLK) g_flag[gt] = 0;
    if (gw >= N) return;

    const int beg = g_rowstart[gw];
    const int end = g_rowstart[gw + 1];
    const float adst = g_adst[gw];

    float m = -3.4e38f;
    float sum = 0.f;
    float4 acc = make_float4(0.f, 0.f, 0.f, 0.f);

    for (int c = beg; c < end; c += 32) {
        int j = c + lane;
        int src = 0;
        float e = -3.4e38f;
        if (j < end) {
            src = g_srcs[j];
            e = g_asrc[src] + adst;
            e = (e >= 0.f) ? e : 0.2f * e;
        }
        float cm = e;
        #pragma unroll
        for (int o = 16; o > 0; o >>= 1) cm = fmaxf(cm, __shfl_xor_sync(0xffffffffu, cm, o));
        float m_new = fmaxf(m, cm);
        float scale = __expf(m - m_new);
        m = m_new;
        sum *= scale;
        acc.x *= scale; acc.y *= scale; acc.z *= scale; acc.w *= scale;

        float w = (j < end) ? __expf(e - m) : 0.f;
        float ws = w;
        #pragma unroll
        for (int o = 16; o > 0; o >>= 1) ws += __shfl_xor_sync(0xffffffffu, ws, o);
        sum += ws;

        int cnt = min(32, end - c);
        if (cnt == 32) {
            #pragma unroll 8
            for (int jj = 0; jj < 32; ++jj) {
                float wj = __shfl_sync(0xffffffffu, w, jj);
                int   sj = __shfl_sync(0xffffffffu, src, jj);
                float4 v = ((const float4*)(g_xp + (size_t)sj * 128))[lane];
                acc.x += wj * v.x; acc.y += wj * v.y;
                acc.z += wj * v.z; acc.w += wj * v.w;
            }
        } else {
            for (int jj = 0; jj < cnt; ++jj) {
                float wj = __shfl_sync(0xffffffffu, w, jj);
                int   sj = __shfl_sync(0xffffffffu, src, jj);
                float4 v = ((const float4*)(g_xp + (size_t)sj * 128))[lane];
                acc.x += wj * v.x; acc.y += wj * v.y;
                acc.z += wj * v.z; acc.w += wj * v.w;
            }
        }
    }

    const float inv = 1.f / sum;
    float4 b4 = ((const float4*)bias)[lane];
    ((float4*)(out + (size_t)gw * 128))[lane] =
        make_float4(acc.x * inv + b4.x, acc.y * inv + b4.y,
                    acc.z * inv + b4.z, acc.w * inv + b4.w);
}

// ---------------- launch (fork-join: edge prep overlaps GEMM) ----------------
extern "C" void kernel_launch(void* const* d_in, const int* in_sizes, int n_in,
                              void* d_out, int out_size) {
    const float* x        = (const float*)d_in[0];
    const float* W        = (const float*)d_in[1];
    const float* att_src  = (const float*)d_in[2];
    const float* att_dst  = (const float*)d_in[3];
    const float* bias     = (const float*)d_in[4];
    const void*  ei       = d_in[5];

    const int N = in_sizes[0] / F;
    const int E = in_sizes[5] / 2;
    const int nblk = (N + SCAN_TILE - 1) / SCAN_TILE;
    float* out = (float*)d_out;

    static cudaStream_t s1 = nullptr;
    static cudaEvent_t e0 = nullptr, e1 = nullptr;
    if (s1 == nullptr) {
        cudaStreamCreateWithFlags(&s1, cudaStreamNonBlocking);
        cudaEventCreateWithFlags(&e0, cudaEventDisableTiming);
        cudaEventCreateWithFlags(&e1, cudaEventDisableTiming);
    }

    // fork: s1 handles the edge-prep chain (independent of GEMM)
    cudaEventRecord(e0, 0);
    cudaStreamWaitEvent(s1, e0, 0);
    k_hist    <<<(E + 1023) / 1024, 256, 0, s1>>>(ei, E);
    k_scanF   <<<nblk, 256, 0, s1>>>(N, E + N);
    k_scatter1<<<(E + 1023) / 1024, 256, 0, s1>>>(ei, E);
    cudaEventRecord(e1, s1);

    // main stream: W split + GEMM in parallel with the prep chain
    k_wsplit <<<64, 256>>>(W);
    k_gemm   <<<(N + 63) / 64, 256>>>(x, att_src, att_dst, N);

    // join, then fused online-softmax aggregation
    cudaStreamWaitEvent(0, e1, 0);
    k_agg    <<<(N + 7) / 8, 256>>>(bias, out, N);
}